// round 1
// baseline (speedup 1.0000x reference)
#include <cuda_runtime.h>
#include <math.h>

#define CAP 262144
#define F   512
#define NB_B 1024
#define ROWS_PER_B (CAP / NB_B)   // 256

// Scratch (allocation-free: __device__ globals)
__device__ float    g_scores[CAP];
__device__ unsigned g_maxbits;
__device__ float    g_partials[NB_B * F];
__device__ float    g_partial_l[NB_B];

// Monotonic float<->uint mapping so atomicMax(uint) == float max (exact, order-independent)
__device__ __forceinline__ unsigned f2o(float f) {
    unsigned u = __float_as_uint(f);
    return (u & 0x80000000u) ? ~u : (u | 0x80000000u);
}
__device__ __forceinline__ float o2f(unsigned o) {
    return (o & 0x80000000u) ? __uint_as_float(o ^ 0x80000000u)
                             : __uint_as_float(~o);
}

__global__ void k_init() { g_maxbits = 0u; }  // 0 < f2o(-inf), safe floor

// Warp-per-row L1 distance: each lane reads 4 float4 (16 floats) of the 512-float row.
__global__ void k_scores(const float* __restrict__ query,
                         const float* __restrict__ keys) {
    __shared__ float4 qs[F / 4];
    int tid = threadIdx.x;
    for (int i = tid; i < F / 4; i += blockDim.x)
        qs[i] = ((const float4*)query)[i];
    __syncthreads();

    int lane  = tid & 31;
    int warp  = tid >> 5;
    int wpb   = blockDim.x >> 5;
    int gwarp = blockIdx.x * wpb + warp;
    int nwarp = gridDim.x * wpb;

    float wmax = -3.4e38f;
    for (int row = gwarp; row < CAP; row += nwarp) {
        const float4* kr = (const float4*)(keys + (size_t)row * F);
        float s = 0.0f;
        #pragma unroll
        for (int j = 0; j < 4; j++) {
            float4 k = kr[lane + 32 * j];
            float4 q = qs[lane + 32 * j];
            s += fabsf(k.x - q.x) + fabsf(k.y - q.y)
               + fabsf(k.z - q.z) + fabsf(k.w - q.w);
        }
        #pragma unroll
        for (int o = 16; o > 0; o >>= 1)
            s += __shfl_xor_sync(0xffffffffu, s, o);
        float sc = -s;                       // butterfly: all lanes hold the sum
        if (lane == 0) g_scores[row] = sc;
        wmax = fmaxf(wmax, sc);
    }
    if (lane == 0) atomicMax(&g_maxbits, f2o(wmax));
}

// Block-per-256-rows weighted accumulation of values. Thread t owns features 4t..4t+3.
__global__ void __launch_bounds__(128) k_accum(const float* __restrict__ values) {
    int tid = threadIdx.x;          // 0..127
    int b   = blockIdx.x;
    float gmax = o2f(g_maxbits);
    const float4* v = (const float4*)values;

    float4 acc = make_float4(0.f, 0.f, 0.f, 0.f);
    float  lsum = 0.0f;
    int row0 = b * ROWS_PER_B;
    #pragma unroll 4
    for (int r = 0; r < ROWS_PER_B; r++) {
        int row = row0 + r;
        float w = __expf(g_scores[row] - gmax);   // broadcast load of score
        float4 val = v[(size_t)row * (F / 4) + tid];
        acc.x += w * val.x;
        acc.y += w * val.y;
        acc.z += w * val.z;
        acc.w += w * val.w;
        lsum  += w;
    }
    ((float4*)g_partials)[b * (F / 4) + tid] = acc;
    if (tid == 0) g_partial_l[b] = lsum;          // identical across threads
}

// Deterministic tree-free final reduce: 4 blocks x 128 threads, one feature each.
__global__ void __launch_bounds__(128) k_final(float* __restrict__ out) {
    int f = blockIdx.x * 128 + threadIdx.x;       // 0..511
    float acc = 0.0f, l = 0.0f;
    #pragma unroll 8
    for (int b = 0; b < NB_B; b++) {
        acc += g_partials[b * F + f];             // coalesced 512B/iter
        l   += g_partial_l[b];                    // broadcast
    }
    float x = acc / l;
    out[f] = 1.0f / (1.0f + __expf(-x));
}

extern "C" void kernel_launch(void* const* d_in, const int* in_sizes, int n_in,
                              void* d_out, int out_size) {
    const float* query  = (const float*)d_in[0];
    const float* keys   = (const float*)d_in[1];
    const float* values = (const float*)d_in[2];
    float* out = (float*)d_out;

    k_init  <<<1, 1>>>();
    k_scores<<<1184, 256>>>(query, keys);   // 148 SMs * 8 blocks, 8 warps each
    k_accum <<<NB_B, 128>>>(values);
    k_final <<<4, 128>>>(out);
}

// round 3
// speedup vs baseline: 1.2011x; 1.2011x over previous
#include <cuda_runtime.h>
#include <math.h>

#define CAP 262144
#define F   512
#define NB_B 1024
#define ROWS_PER_B (CAP / NB_B)   // 256

// Scratch (allocation-free: __device__ globals)
__device__ float    g_scores[CAP];
__device__ unsigned g_maxbits;
__device__ float    g_partials[NB_B * F];
__device__ float    g_partial_l[NB_B];

// Monotonic float<->uint mapping so atomicMax(uint) == float max (exact, order-independent)
__device__ __forceinline__ unsigned f2o(float f) {
    unsigned u = __float_as_uint(f);
    return (u & 0x80000000u) ? ~u : (u | 0x80000000u);
}
__device__ __forceinline__ float o2f(unsigned o) {
    return (o & 0x80000000u) ? __uint_as_float(o ^ 0x80000000u)
                             : __uint_as_float(~o);
}

__global__ void k_init() { g_maxbits = 0u; }  // 0 < f2o(-inf), safe floor

// Warp-per-row L1 distance: each lane reads 4 float4 (16 floats) of the 512-float row.
__global__ void k_scores(const float* __restrict__ query,
                         const float* __restrict__ keys) {
    __shared__ float4 qs[F / 4];
    int tid = threadIdx.x;
    for (int i = tid; i < F / 4; i += blockDim.x)
        qs[i] = ((const float4*)query)[i];
    __syncthreads();

    int lane  = tid & 31;
    int warp  = tid >> 5;
    int wpb   = blockDim.x >> 5;
    int gwarp = blockIdx.x * wpb + warp;
    int nwarp = gridDim.x * wpb;

    float wmax = -3.4e38f;
    for (int row = gwarp; row < CAP; row += nwarp) {
        const float4* kr = (const float4*)(keys + (size_t)row * F);
        float s = 0.0f;
        #pragma unroll
        for (int j = 0; j < 4; j++) {
            float4 k = kr[lane + 32 * j];
            float4 q = qs[lane + 32 * j];
            s += fabsf(k.x - q.x) + fabsf(k.y - q.y)
               + fabsf(k.z - q.z) + fabsf(k.w - q.w);
        }
        #pragma unroll
        for (int o = 16; o > 0; o >>= 1)
            s += __shfl_xor_sync(0xffffffffu, s, o);
        float sc = -s;                       // butterfly: all lanes hold the sum
        if (lane == 0) g_scores[row] = sc;
        wmax = fmaxf(wmax, sc);
    }
    if (lane == 0) atomicMax(&g_maxbits, f2o(wmax));
}

// Block-per-256-rows weighted accumulation of values. Thread t owns features 4t..4t+3.
__global__ void __launch_bounds__(128) k_accum(const float* __restrict__ values) {
    int tid = threadIdx.x;          // 0..127
    int b   = blockIdx.x;
    float gmax = o2f(g_maxbits);
    const float4* v = (const float4*)values;

    float4 acc = make_float4(0.f, 0.f, 0.f, 0.f);
    float  lsum = 0.0f;
    int row0 = b * ROWS_PER_B;
    #pragma unroll 4
    for (int r = 0; r < ROWS_PER_B; r++) {
        int row = row0 + r;
        float w = __expf(g_scores[row] - gmax);   // broadcast load of score
        float4 val = v[(size_t)row * (F / 4) + tid];
        acc.x += w * val.x;
        acc.y += w * val.y;
        acc.z += w * val.z;
        acc.w += w * val.w;
        lsum  += w;
    }
    ((float4*)g_partials)[b * (F / 4) + tid] = acc;
    if (tid == 0) g_partial_l[b] = lsum;          // identical across threads
}

// Parallel deterministic final reduce: one block per feature, fixed-order tree.
__global__ void __launch_bounds__(256) k_final(float* __restrict__ out) {
    __shared__ float sa[256];
    __shared__ float sl[256];
    int f = blockIdx.x;             // 0..511
    int t = threadIdx.x;            // 0..255

    // Each thread folds 4 of the 1024 block-partials for this feature,
    // plus the matching 4 l-partials (loads are L2-resident, high MLP).
    float a = g_partials[(t        ) * F + f]
            + g_partials[(t +  256) * F + f]
            + g_partials[(t +  512) * F + f]
            + g_partials[(t +  768) * F + f];
    float l = g_partial_l[t] + g_partial_l[t + 256]
            + g_partial_l[t + 512] + g_partial_l[t + 768];
    sa[t] = a;
    sl[t] = l;
    __syncthreads();

    #pragma unroll
    for (int s = 128; s > 0; s >>= 1) {
        if (t < s) { sa[t] += sa[t + s]; sl[t] += sl[t + s]; }
        __syncthreads();
    }
    if (t == 0) {
        float x = sa[0] / sl[0];
        out[f] = 1.0f / (1.0f + __expf(-x));
    }
}

extern "C" void kernel_launch(void* const* d_in, const int* in_sizes, int n_in,
                              void* d_out, int out_size) {
    const float* query  = (const float*)d_in[0];
    const float* keys   = (const float*)d_in[1];
    const float* values = (const float*)d_in[2];
    float* out = (float*)d_out;

    k_init  <<<1, 1>>>();
    k_scores<<<1184, 256>>>(query, keys);   // 148 SMs * 8 blocks, 8 warps each
    k_accum <<<NB_B, 128>>>(values);
    k_final <<<F, 256>>>(out);
}

// round 4
// speedup vs baseline: 1.3035x; 1.0853x over previous
#include <cuda_runtime.h>
#include <math.h>

#define CAP 262144
#define F   512
#define NB_B 1024
#define ROWS_PER_B (CAP / NB_B)   // 256
#define CHUNK 28                  // contiguous rows per warp in k_scores
#define NWARPS ((CAP + CHUNK - 1) / CHUNK)          // 9363
#define NBLK_S ((NWARPS + 7) / 8)                   // 1171 blocks of 8 warps

// Scratch (allocation-free: __device__ globals)
__device__ float    g_scores[CAP];
__device__ unsigned g_maxbits;      // static zero-init = safe floor; k_final re-zeros
__device__ float    g_partials[NB_B * F];
__device__ float    g_partial_l[NB_B];

// Monotonic float<->uint mapping so atomicMax(uint) == float max (exact, order-independent)
__device__ __forceinline__ unsigned f2o(float f) {
    unsigned u = __float_as_uint(f);
    return (u & 0x80000000u) ? ~u : (u | 0x80000000u);
}
__device__ __forceinline__ float o2f(unsigned o) {
    return (o & 0x80000000u) ? __uint_as_float(o ^ 0x80000000u)
                             : __uint_as_float(~o);
}

__device__ __forceinline__ float l1_16(float4 k0, float4 k1, float4 k2, float4 k3,
                                       float4 q0, float4 q1, float4 q2, float4 q3) {
    float s = 0.0f;
    s += fabsf(k0.x - q0.x) + fabsf(k0.y - q0.y) + fabsf(k0.z - q0.z) + fabsf(k0.w - q0.w);
    s += fabsf(k1.x - q1.x) + fabsf(k1.y - q1.y) + fabsf(k1.z - q1.z) + fabsf(k1.w - q1.w);
    s += fabsf(k2.x - q2.x) + fabsf(k2.y - q2.y) + fabsf(k2.z - q2.z) + fabsf(k2.w - q2.w);
    s += fabsf(k3.x - q3.x) + fabsf(k3.y - q3.y) + fabsf(k3.z - q3.z) + fabsf(k3.w - q3.w);
    return s;
}

// Warp-per-row L1 distance over a CONTIGUOUS 28-row chunk (56KB) per warp.
// Query held in registers; 2 rows per iter so the shfl chains pipeline.
__global__ void __launch_bounds__(256) k_scores(const float* __restrict__ query,
                                                const float* __restrict__ keys) {
    int tid   = threadIdx.x;
    int lane  = tid & 31;
    int warp  = tid >> 5;
    int gwarp = blockIdx.x * 8 + warp;

    // query is 2KB; L1/L2-resident broadcast loads
    const float4* qv = (const float4*)query;
    float4 q0 = qv[lane], q1 = qv[lane + 32], q2 = qv[lane + 64], q3 = qv[lane + 96];

    int row     = gwarp * CHUNK;
    if (row >= CAP) return;
    int row_end = min(row + CHUNK, CAP);

    float wmax = -3.4e38f;
    for (; row + 2 <= row_end; row += 2) {
        const float4* ka = (const float4*)(keys + (size_t)row * F);
        const float4* kb = ka + (F / 4);
        float sa = l1_16(ka[lane], ka[lane + 32], ka[lane + 64], ka[lane + 96],
                         q0, q1, q2, q3);
        float sb = l1_16(kb[lane], kb[lane + 32], kb[lane + 64], kb[lane + 96],
                         q0, q1, q2, q3);
        #pragma unroll
        for (int o = 16; o > 0; o >>= 1) {          // two independent chains, ILP
            sa += __shfl_xor_sync(0xffffffffu, sa, o);
            sb += __shfl_xor_sync(0xffffffffu, sb, o);
        }
        float na = -sa, nb = -sb;
        if (lane == 0) { g_scores[row] = na; g_scores[row + 1] = nb; }
        wmax = fmaxf(wmax, fmaxf(na, nb));
    }
    if (row < row_end) {
        const float4* ka = (const float4*)(keys + (size_t)row * F);
        float sa = l1_16(ka[lane], ka[lane + 32], ka[lane + 64], ka[lane + 96],
                         q0, q1, q2, q3);
        #pragma unroll
        for (int o = 16; o > 0; o >>= 1)
            sa += __shfl_xor_sync(0xffffffffu, sa, o);
        float na = -sa;
        if (lane == 0) g_scores[row] = na;
        wmax = fmaxf(wmax, na);
    }
    if (lane == 0) atomicMax(&g_maxbits, f2o(wmax));
}

// Block-per-256-contiguous-rows weighted accumulation. Thread t owns features 4t..4t+3.
__global__ void __launch_bounds__(128) k_accum(const float* __restrict__ values) {
    int tid = threadIdx.x;          // 0..127
    int b   = blockIdx.x;
    float gmax = o2f(g_maxbits);
    const float4* v = (const float4*)values;

    float4 acc = make_float4(0.f, 0.f, 0.f, 0.f);
    float  lsum = 0.0f;
    int row0 = b * ROWS_PER_B;
    #pragma unroll 8
    for (int r = 0; r < ROWS_PER_B; r++) {
        int row = row0 + r;
        float w = __expf(g_scores[row] - gmax);   // broadcast load of score
        float4 val = v[(size_t)row * (F / 4) + tid];
        acc.x += w * val.x;
        acc.y += w * val.y;
        acc.z += w * val.z;
        acc.w += w * val.w;
        lsum  += w;
    }
    ((float4*)g_partials)[b * (F / 4) + tid] = acc;
    if (tid == 0) g_partial_l[b] = lsum;          // identical across threads
}

// Parallel deterministic final reduce: one block per feature, fixed-order tree.
// Also re-zeros g_maxbits for the next graph replay (stream-ordered, safe).
__global__ void __launch_bounds__(256) k_final(float* __restrict__ out) {
    __shared__ float sa[256];
    __shared__ float sl[256];
    int f = blockIdx.x;             // 0..511
    int t = threadIdx.x;            // 0..255

    if (f == 0 && t == 0) g_maxbits = 0u;         // reset for next replay

    float a = g_partials[(t        ) * F + f]
            + g_partials[(t +  256) * F + f]
            + g_partials[(t +  512) * F + f]
            + g_partials[(t +  768) * F + f];
    float l = g_partial_l[t] + g_partial_l[t + 256]
            + g_partial_l[t + 512] + g_partial_l[t + 768];
    sa[t] = a;
    sl[t] = l;
    __syncthreads();

    #pragma unroll
    for (int s = 128; s > 0; s >>= 1) {
        if (t < s) { sa[t] += sa[t + s]; sl[t] += sl[t + s]; }
        __syncthreads();
    }
    if (t == 0) {
        float x = sa[0] / sl[0];
        out[f] = 1.0f / (1.0f + __expf(-x));
    }
}

extern "C" void kernel_launch(void* const* d_in, const int* in_sizes, int n_in,
                              void* d_out, int out_size) {
    const float* query  = (const float*)d_in[0];
    const float* keys   = (const float*)d_in[1];
    const float* values = (const float*)d_in[2];
    float* out = (float*)d_out;

    k_scores<<<NBLK_S, 256>>>(query, keys);
    k_accum <<<NB_B, 128>>>(values);
    k_final <<<F, 256>>>(out);
}

// round 5
// speedup vs baseline: 1.3257x; 1.0170x over previous
#include <cuda_runtime.h>
#include <math.h>

#define CAP 262144
#define F   512
#define NB_B 1024
#define ROWS_PER_B (CAP / NB_B)   // 256
#define SBLK 888                  // 148 SMs * 6 resident blocks = one exact wave
#define SWARPS (SBLK * 8)         // 7104 warps

// Scratch (allocation-free: __device__ globals)
__device__ float    g_scores[CAP];
__device__ unsigned g_maxbits;      // static zero-init = safe floor; k_final re-zeros
__device__ float    g_partials[NB_B * F];
__device__ float    g_partial_l[NB_B];

// Monotonic float<->uint mapping so atomicMax(uint) == float max (exact, order-independent)
__device__ __forceinline__ unsigned f2o(float f) {
    unsigned u = __float_as_uint(f);
    return (u & 0x80000000u) ? ~u : (u | 0x80000000u);
}
__device__ __forceinline__ float o2f(unsigned o) {
    return (o & 0x80000000u) ? __uint_as_float(o ^ 0x80000000u)
                             : __uint_as_float(~o);
}

__device__ __forceinline__ float l1_16(float4 k0, float4 k1, float4 k2, float4 k3,
                                       float4 q0, float4 q1, float4 q2, float4 q3) {
    float s = 0.0f;
    s += fabsf(k0.x - q0.x) + fabsf(k0.y - q0.y) + fabsf(k0.z - q0.z) + fabsf(k0.w - q0.w);
    s += fabsf(k1.x - q1.x) + fabsf(k1.y - q1.y) + fabsf(k1.z - q1.z) + fabsf(k1.w - q1.w);
    s += fabsf(k2.x - q2.x) + fabsf(k2.y - q2.y) + fabsf(k2.z - q2.z) + fabsf(k2.w - q2.w);
    s += fabsf(k3.x - q3.x) + fabsf(k3.y - q3.y) + fabsf(k3.z - q3.z) + fabsf(k3.w - q3.w);
    return s;
}

// Warp-per-row L1 distance. One exact wave: 888 blocks x 8 warps; warp g owns the
// contiguous balanced row range [g*CAP/G, (g+1)*CAP/G)  (37 or 38 rows, ~75KB).
__global__ void __launch_bounds__(256, 6) k_scores(const float* __restrict__ query,
                                                   const float* __restrict__ keys) {
    int tid   = threadIdx.x;
    int lane  = tid & 31;
    int warp  = tid >> 5;
    int gwarp = blockIdx.x * 8 + warp;

    // query is 2KB; L1/L2-resident broadcast loads
    const float4* qv = (const float4*)query;
    float4 q0 = qv[lane], q1 = qv[lane + 32], q2 = qv[lane + 64], q3 = qv[lane + 96];

    int row     = (int)(((long long)gwarp       * CAP) / SWARPS);
    int row_end = (int)(((long long)(gwarp + 1) * CAP) / SWARPS);

    float wmax = -3.4e38f;
    for (; row + 2 <= row_end; row += 2) {
        const float4* ka = (const float4*)(keys + (size_t)row * F);
        const float4* kb = ka + (F / 4);
        float sa = l1_16(__ldcs(ka + lane),      __ldcs(ka + lane + 32),
                         __ldcs(ka + lane + 64), __ldcs(ka + lane + 96),
                         q0, q1, q2, q3);
        float sb = l1_16(__ldcs(kb + lane),      __ldcs(kb + lane + 32),
                         __ldcs(kb + lane + 64), __ldcs(kb + lane + 96),
                         q0, q1, q2, q3);
        #pragma unroll
        for (int o = 16; o > 0; o >>= 1) {          // two independent chains, ILP
            sa += __shfl_xor_sync(0xffffffffu, sa, o);
            sb += __shfl_xor_sync(0xffffffffu, sb, o);
        }
        float na = -sa, nb = -sb;
        if (lane == 0) { g_scores[row] = na; g_scores[row + 1] = nb; }
        wmax = fmaxf(wmax, fmaxf(na, nb));
    }
    if (row < row_end) {
        const float4* ka = (const float4*)(keys + (size_t)row * F);
        float sa = l1_16(__ldcs(ka + lane),      __ldcs(ka + lane + 32),
                         __ldcs(ka + lane + 64), __ldcs(ka + lane + 96),
                         q0, q1, q2, q3);
        #pragma unroll
        for (int o = 16; o > 0; o >>= 1)
            sa += __shfl_xor_sync(0xffffffffu, sa, o);
        float na = -sa;
        if (lane == 0) g_scores[row] = na;
        wmax = fmaxf(wmax, na);
    }
    atomicMax(&g_maxbits, f2o(wmax));   // all lanes same value post-butterfly? no —
    // wmax is per-lane identical only for the reduced scores; lane-local wmax IS
    // identical across lanes (built from post-butterfly values), so one atomic per
    // warp suffices; keep it lane0-only to halve atomic traffic:
}

// Block-per-256-contiguous-rows weighted accumulation. Thread t owns features 4t..4t+3.
__global__ void __launch_bounds__(128) k_accum(const float* __restrict__ values) {
    int tid = threadIdx.x;          // 0..127
    int b   = blockIdx.x;
    float gmax = o2f(g_maxbits);
    const float4* v = (const float4*)values;

    float4 acc = make_float4(0.f, 0.f, 0.f, 0.f);
    float  lsum = 0.0f;
    int row0 = b * ROWS_PER_B;
    #pragma unroll 8
    for (int r = 0; r < ROWS_PER_B; r++) {
        int row = row0 + r;
        float w = __expf(g_scores[row] - gmax);   // broadcast load of score
        float4 val = __ldcs(v + (size_t)row * (F / 4) + tid);
        acc.x += w * val.x;
        acc.y += w * val.y;
        acc.z += w * val.z;
        acc.w += w * val.w;
        lsum  += w;
    }
    ((float4*)g_partials)[b * (F / 4) + tid] = acc;
    if (tid == 0) g_partial_l[b] = lsum;          // identical across threads
}

// Parallel deterministic final reduce: one block per feature, fixed-order tree.
// Also re-zeros g_maxbits for the next graph replay (stream-ordered, safe).
__global__ void __launch_bounds__(256) k_final(float* __restrict__ out) {
    __shared__ float sa[256];
    __shared__ float sl[256];
    int f = blockIdx.x;             // 0..511
    int t = threadIdx.x;            // 0..255

    if (f == 0 && t == 0) g_maxbits = 0u;         // reset for next replay

    float a = g_partials[(t        ) * F + f]
            + g_partials[(t +  256) * F + f]
            + g_partials[(t +  512) * F + f]
            + g_partials[(t +  768) * F + f];
    float l = g_partial_l[t] + g_partial_l[t + 256]
            + g_partial_l[t + 512] + g_partial_l[t + 768];
    sa[t] = a;
    sl[t] = l;
    __syncthreads();

    #pragma unroll
    for (int s = 128; s > 0; s >>= 1) {
        if (t < s) { sa[t] += sa[t + s]; sl[t] += sl[t + s]; }
        __syncthreads();
    }
    if (t == 0) {
        float x = sa[0] / sl[0];
        out[f] = 1.0f / (1.0f + __expf(-x));
    }
}

extern "C" void kernel_launch(void* const* d_in, const int* in_sizes, int n_in,
                              void* d_out, int out_size) {
    const float* query  = (const float*)d_in[0];
    const float* keys   = (const float*)d_in[1];
    const float* values = (const float*)d_in[2];
    float* out = (float*)d_out;

    k_scores<<<SBLK, 256>>>(query, keys);
    k_accum <<<NB_B, 128>>>(values);
    k_final <<<F, 256>>>(out);
}